// round 9
// baseline (speedup 1.0000x reference)
#include <cuda_runtime.h>
#include <float.h>
#include <math.h>
#include <stdint.h>

#define BB 8
#define LL 2048
#define DIN 256
#define DATT 128

// scratch for projected/ELU'd (tf32-rounded) matrices
__device__ float g_inp[BB * LL * DATT];   // elu(context @ W_in)
__device__ float g_mem[BB * LL * DATT];   // elu(query  @ W_mem)

__device__ __forceinline__ float elu01(float v) {
    return v > 0.0f ? v : 0.01f * expm1f(v);
}
__device__ __forceinline__ float f2tf(float v) {
    uint32_t r;
    asm("cvt.rna.tf32.f32 %0, %1;" : "=r"(r) : "f"(v));
    return __uint_as_float(r);
}
__device__ __forceinline__ float fex2(float x) {
    float r;
    asm("ex2.approx.f32 %0, %1;" : "=f"(r) : "f"(x));
    return r;
}
__device__ __forceinline__ uint32_t fu(float v) { return __float_as_uint(v); }

__device__ __forceinline__ void mma8(float d[4],
                                     uint32_t a0, uint32_t a1, uint32_t a2, uint32_t a3,
                                     uint32_t b0, uint32_t b1) {
    asm volatile(
        "mma.sync.aligned.m16n8k8.row.col.f32.tf32.tf32.f32 "
        "{%0,%1,%2,%3},{%4,%5,%6,%7},{%8,%9},{%0,%1,%2,%3};\n"
        : "+f"(d[0]), "+f"(d[1]), "+f"(d[2]), "+f"(d[3])
        : "r"(a0), "r"(a1), "r"(a2), "r"(a3), "r"(b0), "r"(b1));
}

// ---------------------------------------------------------------------------
// Kernel 1: projections on tensor cores (unchanged from the 231.5us build).
// grid = (16384/128, 2), block = 256.  O = tf32(elu(X @ W)).
// ---------------------------------------------------------------------------
__global__ __launch_bounds__(256) void proj_kernel(
    const float* __restrict__ ctx, const float* __restrict__ qry,
    const float* __restrict__ Win, const float* __restrict__ Wmem)
{
    const int which = blockIdx.y;
    const float* X = (which == 0) ? ctx : qry;
    const float* W = (which == 0) ? Win : Wmem;
    float* O = (which == 0) ? g_inp : g_mem;

    __shared__ float Xs[128 * 36];
    __shared__ float Ws[32 * 136];

    const int tid  = threadIdx.x;
    const int w    = tid >> 5;
    const int lane = tid & 31;
    const int g = lane >> 2;
    const int t = lane & 3;
    const int r0 = (w >> 1) * 32;
    const int n0 = (w & 1) * 64;
    const int m0 = blockIdx.x * 128;

    float acc[2][8][4];
#pragma unroll
    for (int mi = 0; mi < 2; mi++)
#pragma unroll
        for (int j = 0; j < 8; j++)
#pragma unroll
            for (int r = 0; r < 4; r++) acc[mi][j][r] = 0.f;

    for (int kt = 0; kt < 8; kt++) {
#pragma unroll
        for (int i = 0; i < 4; i++) {
            int idx = tid + i * 256;
            int row = idx >> 3, c4 = idx & 7;
            *reinterpret_cast<float4*>(&Xs[row * 36 + c4 * 4]) =
                *reinterpret_cast<const float4*>(
                    &X[(size_t)(m0 + row) * DIN + kt * 32 + c4 * 4]);
        }
#pragma unroll
        for (int i = 0; i < 4; i++) {
            int idx = tid + i * 256;
            int row = idx >> 5, c = idx & 31;
            *reinterpret_cast<float4*>(&Ws[row * 136 + c * 4]) =
                *reinterpret_cast<const float4*>(
                    &W[(size_t)(kt * 32 + row) * DATT + c * 4]);
        }
        __syncthreads();

#pragma unroll
        for (int ks = 0; ks < 4; ks++) {
            int k0 = ks * 8;
            uint32_t a[2][4];
#pragma unroll
            for (int mi = 0; mi < 2; mi++) {
                int rr = r0 + 16 * mi + g;
                a[mi][0] = fu(Xs[rr * 36 + k0 + t]);
                a[mi][1] = fu(Xs[(rr + 8) * 36 + k0 + t]);
                a[mi][2] = fu(Xs[rr * 36 + k0 + t + 4]);
                a[mi][3] = fu(Xs[(rr + 8) * 36 + k0 + t + 4]);
            }
#pragma unroll
            for (int j = 0; j < 8; j++) {
                uint32_t b0 = fu(Ws[(k0 + t) * 136 + n0 + 8 * j + g]);
                uint32_t b1 = fu(Ws[(k0 + t + 4) * 136 + n0 + 8 * j + g]);
#pragma unroll
                for (int mi = 0; mi < 2; mi++)
                    mma8(acc[mi][j], a[mi][0], a[mi][1], a[mi][2], a[mi][3], b0, b1);
            }
        }
        __syncthreads();
    }

#pragma unroll
    for (int mi = 0; mi < 2; mi++) {
        size_t rb0 = (size_t)(m0 + r0 + 16 * mi + g) * DATT;
        size_t rb1 = rb0 + (size_t)8 * DATT;
#pragma unroll
        for (int j = 0; j < 8; j++) {
            int cl = n0 + 8 * j + 2 * t;
            *reinterpret_cast<float2*>(&O[rb0 + cl]) =
                make_float2(f2tf(elu01(acc[mi][j][0])), f2tf(elu01(acc[mi][j][1])));
            *reinterpret_cast<float2*>(&O[rb1 + cl]) =
                make_float2(f2tf(elu01(acc[mi][j][2])), f2tf(elu01(acc[mi][j][3])));
        }
    }
}

// ---------------------------------------------------------------------------
// Kernel 2: fused flash attention, tf32 mma, fixed-max softmax.
// 2 CTAs/SM for barrier decoupling: TQ=64, TK=32, 256 threads (8 warps).
// grid = (32, 8) = 256 CTAs, ~94.3KB smem each -> 2 resident per SM.
// ---------------------------------------------------------------------------
#define TQ 64    // c-tile rows per CTA
#define TK 32    // q-tile per iteration
#define QP 132   // Qs/Ks pitch
#define VP 264   // Vs pitch (mod 32 == 8 -> conflict-free B-frag loads)
#define PP 36    // Ps pitch

#define OFF_Q   0
#define OFF_K   (OFF_Q + TQ * QP)     // 8448
#define OFF_V   (OFF_K + TK * QP)     // 12672
#define OFF_P   (OFF_V + TK * VP)     // 21120
#define OFF_L   (OFF_P + TQ * PP)     // 23424
#define OFF_MSK (OFF_L + 2 * TQ)      // 23552
#define SMEMF   (OFF_MSK + TK)        // 23584 floats
#define SMEMB   (SMEMF * 4)           // 94336 bytes

__global__ __launch_bounds__(256, 2) void attn_kernel(
    const float* __restrict__ qryV,      // query (V role), [B,L,256]
    const int*   __restrict__ qmask,     // [B,L]
    float*       __restrict__ out)       // [B,L,256]
{
    extern __shared__ float sm[];
    float* Qs   = sm + OFF_Q;
    float* Ks   = sm + OFF_K;
    float* Vs   = sm + OFF_V;
    float* Ps   = sm + OFF_P;
    float* redL = sm + OFF_L;
    int*   vmsk = reinterpret_cast<int*>(sm + OFF_MSK);

    const int b   = blockIdx.y;
    const int c0  = blockIdx.x * TQ;
    const int tid = threadIdx.x;
    const int w    = tid >> 5;
    const int lane = tid & 31;
    const int g = lane >> 2;
    const int t = lane & 3;
    const int wr  = w >> 1, wc  = w & 1;    // GEMM1: 4 rowgrp x 2 colgrp
    const int wr2 = w >> 2, wc2 = w & 3;    // GEMM2: 2 rowgrp x 4 colgrp
    const int r0  = wr * 16;                // GEMM1 rows (16 per warp)
    const int nq0 = wc * 16;                // GEMM1 cols (16 per warp)
    const int r2  = wr2 * 32;               // GEMM2 rows (32 per warp)
    const int n2  = wc2 * 64;               // GEMM2 cols (64 per warp)
    const float cs = 0.12751743f;           // (1/sqrt(128)) * log2(e)

    // Q tile: 64x128 = 2048 float4 / 256 thr = 8 each
#pragma unroll
    for (int i = 0; i < 8; i++) {
        int idx = tid + i * 256;
        int row = idx >> 5, k4 = idx & 31;
        *reinterpret_cast<float4*>(&Qs[row * QP + k4 * 4]) =
            *reinterpret_cast<const float4*>(
                &g_inp[(size_t)(b * LL + c0 + row) * DATT + k4 * 4]);
    }

    float o[2][8][4];
#pragma unroll
    for (int mi = 0; mi < 2; mi++)
#pragma unroll
        for (int j = 0; j < 8; j++)
#pragma unroll
            for (int r = 0; r < 4; r++) o[mi][j][r] = 0.f;
    float lsum0 = 0.f, lsum1 = 0.f;

#pragma unroll 1
    for (int q0 = 0; q0 < LL; q0 += TK) {
        __syncthreads();   // prev GEMM2 done with Ks/Vs/Ps

        // K tile: 32x128 = 1024 float4 / 256 = 4 each
#pragma unroll
        for (int i = 0; i < 4; i++) {
            int idx = tid + i * 256;
            int row = idx >> 5, k4 = idx & 31;
            *reinterpret_cast<float4*>(&Ks[row * QP + k4 * 4]) =
                *reinterpret_cast<const float4*>(
                    &g_mem[(size_t)(b * LL + q0 + row) * DATT + k4 * 4]);
        }
        // V tile: 32x256 = 2048 float4 / 256 = 8 each (tf32-round)
#pragma unroll
        for (int i = 0; i < 8; i++) {
            int idx = tid + i * 256;
            int row = idx >> 6, v4 = idx & 63;
            float4 v = *reinterpret_cast<const float4*>(
                &qryV[(size_t)(b * LL + q0 + row) * DIN + v4 * 4]);
            v.x = f2tf(v.x); v.y = f2tf(v.y); v.z = f2tf(v.z); v.w = f2tf(v.w);
            *reinterpret_cast<float4*>(&Vs[row * VP + v4 * 4]) = v;
        }
        if (tid < TK) vmsk[tid] = qmask[b * LL + q0 + tid];
        __syncthreads();

        // ---- GEMM1: S[64,32] = Q.K^T, warp tile 16x16 ----
        float s[2][4];
#pragma unroll
        for (int j = 0; j < 2; j++)
#pragma unroll
            for (int r = 0; r < 4; r++) s[j][r] = 0.f;

#pragma unroll
        for (int k0 = 0; k0 < DATT; k0 += 8) {
            uint32_t a0 = fu(Qs[(r0 + g) * QP + k0 + t]);
            uint32_t a1 = fu(Qs[(r0 + g + 8) * QP + k0 + t]);
            uint32_t a2 = fu(Qs[(r0 + g) * QP + k0 + t + 4]);
            uint32_t a3 = fu(Qs[(r0 + g + 8) * QP + k0 + t + 4]);
#pragma unroll
            for (int j = 0; j < 2; j++) {
                uint32_t b0 = fu(Ks[(nq0 + 8 * j + g) * QP + k0 + t]);
                uint32_t b1 = fu(Ks[(nq0 + 8 * j + g) * QP + k0 + t + 4]);
                mma8(s[j], a0, a1, a2, a3, b0, b1);
            }
        }

        // ---- fixed-max softmax: p = exp2(s*cs), masked -> 0 ----
        {
            const int cg0 = c0 + r0 + g, cg1 = cg0 + 8;
            float su0 = 0.f, su1 = 0.f;
#pragma unroll
            for (int j = 0; j < 2; j++) {
                int cl = nq0 + 8 * j + 2 * t;
                bool v0 = vmsk[cl] > 0, v1 = vmsk[cl + 1] > 0;
                int qg0 = q0 + cl, qg1 = qg0 + 1;
                float p00 = (v0 && cg0 != qg0) ? fex2(s[j][0] * cs) : 0.f;
                float p01 = (v1 && cg0 != qg1) ? fex2(s[j][1] * cs) : 0.f;
                float p10 = (v0 && cg1 != qg0) ? fex2(s[j][2] * cs) : 0.f;
                float p11 = (v1 && cg1 != qg1) ? fex2(s[j][3] * cs) : 0.f;
                su0 += p00 + p01;
                su1 += p10 + p11;
                *reinterpret_cast<float2*>(&Ps[(r0 + g) * PP + cl]) =
                    make_float2(f2tf(p00), f2tf(p01));
                *reinterpret_cast<float2*>(&Ps[(r0 + g + 8) * PP + cl]) =
                    make_float2(f2tf(p10), f2tf(p11));
            }
            su0 += __shfl_xor_sync(0xffffffffu, su0, 1);
            su0 += __shfl_xor_sync(0xffffffffu, su0, 2);
            su1 += __shfl_xor_sync(0xffffffffu, su1, 1);
            su1 += __shfl_xor_sync(0xffffffffu, su1, 2);
            lsum0 += su0;
            lsum1 += su1;
        }
        __syncthreads();   // Ps ready

        // ---- GEMM2: O[64,256] += P[64,32] . V[32,256], warp tile 32x64 ----
#pragma unroll
        for (int k0 = 0; k0 < TK; k0 += 8) {
            uint32_t a[2][4];
#pragma unroll
            for (int mi = 0; mi < 2; mi++) {
                int rr = r2 + 16 * mi + g;
                a[mi][0] = fu(Ps[rr * PP + k0 + t]);
                a[mi][1] = fu(Ps[(rr + 8) * PP + k0 + t]);
                a[mi][2] = fu(Ps[rr * PP + k0 + t + 4]);
                a[mi][3] = fu(Ps[(rr + 8) * PP + k0 + t + 4]);
            }
#pragma unroll
            for (int j = 0; j < 8; j++) {
                uint32_t b0 = fu(Vs[(k0 + t) * VP + n2 + 8 * j + g]);
                uint32_t b1 = fu(Vs[(k0 + t + 4) * VP + n2 + 8 * j + g]);
#pragma unroll
                for (int mi = 0; mi < 2; mi++)
                    mma8(o[mi][j], a[mi][0], a[mi][1], a[mi][2], a[mi][3], b0, b1);
            }
        }
    }

    // ---- per-colgroup row sums -> normalize + store ----
    if (t == 0) {
        redL[wc * TQ + r0 + g]     = lsum0;
        redL[wc * TQ + r0 + g + 8] = lsum1;
    }
    __syncthreads();

#pragma unroll
    for (int mi = 0; mi < 2; mi++) {
        int rr0 = r2 + 16 * mi + g;
        int rr1 = rr0 + 8;
        float l0 = 1.0f / (redL[rr0] + redL[TQ + rr0]);
        float l1 = 1.0f / (redL[rr1] + redL[TQ + rr1]);
        size_t rb0 = (size_t)(b * LL + c0 + rr0) * DIN;
        size_t rb1 = (size_t)(b * LL + c0 + rr1) * DIN;
#pragma unroll
        for (int j = 0; j < 8; j++) {
            int cl = n2 + 8 * j + 2 * t;
            *reinterpret_cast<float2*>(&out[rb0 + cl]) =
                make_float2(o[mi][j][0] * l0, o[mi][j][1] * l0);
            *reinterpret_cast<float2*>(&out[rb1 + cl]) =
                make_float2(o[mi][j][2] * l1, o[mi][j][3] * l1);
        }
    }
}

// ---------------------------------------------------------------------------
extern "C" void kernel_launch(void* const* d_in, const int* in_sizes, int n_in,
                              void* d_out, int out_size)
{
    const float* ctx  = (const float*)d_in[0];
    const float* qry  = (const float*)d_in[1];
    const float* Win  = (const float*)d_in[2];
    const float* Wmem = (const float*)d_in[3];
    const int*   msk  = (const int*)d_in[4];
    float* out = (float*)d_out;

    (void)in_sizes; (void)n_in; (void)out_size;

    cudaFuncSetAttribute(attn_kernel,
                         cudaFuncAttributeMaxDynamicSharedMemorySize, SMEMB);

    proj_kernel<<<dim3(BB * LL / 128, 2), 256>>>(ctx, qry, Win, Wmem);
    attn_kernel<<<dim3(LL / TQ, BB), 256, SMEMB>>>(qry, msk, out);
}

// round 10
// speedup vs baseline: 1.1910x; 1.1910x over previous
#include <cuda_runtime.h>
#include <float.h>
#include <math.h>
#include <stdint.h>

#define BB 8
#define LL 2048
#define DIN 256
#define DATT 128

// scratch for projected/ELU'd (tf32-rounded) matrices
__device__ float g_inp[BB * LL * DATT];   // elu(context @ W_in)
__device__ float g_mem[BB * LL * DATT];   // elu(query  @ W_mem)

__device__ __forceinline__ float elu01(float v) {
    return v > 0.0f ? v : 0.01f * expm1f(v);
}
__device__ __forceinline__ float f2tf(float v) {
    uint32_t r;
    asm("cvt.rna.tf32.f32 %0, %1;" : "=r"(r) : "f"(v));
    return __uint_as_float(r);
}
__device__ __forceinline__ float fex2(float x) {
    float r;
    asm("ex2.approx.f32 %0, %1;" : "=f"(r) : "f"(x));
    return r;
}
__device__ __forceinline__ uint32_t fu(float v) { return __float_as_uint(v); }

__device__ __forceinline__ void mma8(float d[4],
                                     uint32_t a0, uint32_t a1, uint32_t a2, uint32_t a3,
                                     uint32_t b0, uint32_t b1) {
    asm volatile(
        "mma.sync.aligned.m16n8k8.row.col.f32.tf32.tf32.f32 "
        "{%0,%1,%2,%3},{%4,%5,%6,%7},{%8,%9},{%0,%1,%2,%3};\n"
        : "+f"(d[0]), "+f"(d[1]), "+f"(d[2]), "+f"(d[3])
        : "r"(a0), "r"(a1), "r"(a2), "r"(a3), "r"(b0), "r"(b1));
}

// ---------------------------------------------------------------------------
// Kernel 1: projections on tensor cores (unchanged from the 231.5us build).
// grid = (16384/128, 2), block = 256.  O = tf32(elu(X @ W)).
// ---------------------------------------------------------------------------
__global__ __launch_bounds__(256) void proj_kernel(
    const float* __restrict__ ctx, const float* __restrict__ qry,
    const float* __restrict__ Win, const float* __restrict__ Wmem)
{
    const int which = blockIdx.y;
    const float* X = (which == 0) ? ctx : qry;
    const float* W = (which == 0) ? Win : Wmem;
    float* O = (which == 0) ? g_inp : g_mem;

    __shared__ float Xs[128 * 36];
    __shared__ float Ws[32 * 136];

    const int tid  = threadIdx.x;
    const int w    = tid >> 5;
    const int lane = tid & 31;
    const int g = lane >> 2;
    const int t = lane & 3;
    const int r0 = (w >> 1) * 32;
    const int n0 = (w & 1) * 64;
    const int m0 = blockIdx.x * 128;

    float acc[2][8][4];
#pragma unroll
    for (int mi = 0; mi < 2; mi++)
#pragma unroll
        for (int j = 0; j < 8; j++)
#pragma unroll
            for (int r = 0; r < 4; r++) acc[mi][j][r] = 0.f;

    for (int kt = 0; kt < 8; kt++) {
#pragma unroll
        for (int i = 0; i < 4; i++) {
            int idx = tid + i * 256;
            int row = idx >> 3, c4 = idx & 7;
            *reinterpret_cast<float4*>(&Xs[row * 36 + c4 * 4]) =
                *reinterpret_cast<const float4*>(
                    &X[(size_t)(m0 + row) * DIN + kt * 32 + c4 * 4]);
        }
#pragma unroll
        for (int i = 0; i < 4; i++) {
            int idx = tid + i * 256;
            int row = idx >> 5, c = idx & 31;
            *reinterpret_cast<float4*>(&Ws[row * 136 + c * 4]) =
                *reinterpret_cast<const float4*>(
                    &W[(size_t)(kt * 32 + row) * DATT + c * 4]);
        }
        __syncthreads();

#pragma unroll
        for (int ks = 0; ks < 4; ks++) {
            int k0 = ks * 8;
            uint32_t a[2][4];
#pragma unroll
            for (int mi = 0; mi < 2; mi++) {
                int rr = r0 + 16 * mi + g;
                a[mi][0] = fu(Xs[rr * 36 + k0 + t]);
                a[mi][1] = fu(Xs[(rr + 8) * 36 + k0 + t]);
                a[mi][2] = fu(Xs[rr * 36 + k0 + t + 4]);
                a[mi][3] = fu(Xs[(rr + 8) * 36 + k0 + t + 4]);
            }
#pragma unroll
            for (int j = 0; j < 8; j++) {
                uint32_t b0 = fu(Ws[(k0 + t) * 136 + n0 + 8 * j + g]);
                uint32_t b1 = fu(Ws[(k0 + t + 4) * 136 + n0 + 8 * j + g]);
#pragma unroll
                for (int mi = 0; mi < 2; mi++)
                    mma8(acc[mi][j], a[mi][0], a[mi][1], a[mi][2], a[mi][3], b0, b1);
            }
        }
        __syncthreads();
    }

#pragma unroll
    for (int mi = 0; mi < 2; mi++) {
        size_t rb0 = (size_t)(m0 + r0 + 16 * mi + g) * DATT;
        size_t rb1 = rb0 + (size_t)8 * DATT;
#pragma unroll
        for (int j = 0; j < 8; j++) {
            int cl = n0 + 8 * j + 2 * t;
            *reinterpret_cast<float2*>(&O[rb0 + cl]) =
                make_float2(f2tf(elu01(acc[mi][j][0])), f2tf(elu01(acc[mi][j][1])));
            *reinterpret_cast<float2*>(&O[rb1 + cl]) =
                make_float2(f2tf(elu01(acc[mi][j][2])), f2tf(elu01(acc[mi][j][3])));
        }
    }
}

// ---------------------------------------------------------------------------
// Kernel 2: fused flash attention, tf32 mma, fixed-max softmax,
// prefetch-pipelined tiles.  grid = (16, 8), block = 512 (16 warps).
// Per-iter: GEMM1 -> [LDG K(i+1)] -> softmax -> syncC -> STS Ks -> GEMM2
//           -> [LDG V(i+1)] -> syncA -> cvt+STS Vs -> syncB.
// All global-load latency overlaps compute or barrier drain.
// ---------------------------------------------------------------------------
#define TQ 128   // c-tile rows
#define TK 64    // q-tile
#define QP 132   // Qs/Ks pitch
#define VP 264   // Vs pitch (mod 32 == 8 -> conflict-free B-frag loads)
#define PP 68    // Ps pitch

#define OFF_Q   0
#define OFF_K   (OFF_Q + TQ * QP)              // 16896
#define OFF_V   (OFF_K + TK * QP)              // 25344
#define OFF_P   (OFF_V + TK * VP)              // 42240
#define OFF_L   (OFF_P + TQ * PP)              // 50944
#define OFF_MSK (OFF_L + 2 * TQ)               // 51200
#define SMEMF   (OFF_MSK + TK)                 // 51264 floats
#define SMEMB   (SMEMF * 4)                    // 205056 bytes

__global__ __launch_bounds__(512, 1) void attn_kernel(
    const float* __restrict__ qryV,      // query (V role), [B,L,256]
    const int*   __restrict__ qmask,     // [B,L]
    float*       __restrict__ out)       // [B,L,256]
{
    extern __shared__ float sm[];
    float* Qs   = sm + OFF_Q;
    float* Ks   = sm + OFF_K;
    float* Vs   = sm + OFF_V;
    float* Ps   = sm + OFF_P;
    float* redL = sm + OFF_L;
    int*   vmsk = reinterpret_cast<int*>(sm + OFF_MSK);

    const int b   = blockIdx.y;
    const int c0  = blockIdx.x * TQ;
    const int tid = threadIdx.x;
    const int w    = tid >> 5;
    const int lane = tid & 31;
    const int g = lane >> 2;
    const int t = lane & 3;
    const int wr  = w >> 1, wc  = w & 1;    // GEMM1: 8 rowgrp x 2 colgrp
    const int wr2 = w >> 2, wc2 = w & 3;    // GEMM2: 4 rowgrp x 4 colgrp
    const int r0  = wr * 16;
    const int nq0 = wc * 32;
    const int r2  = wr2 * 32;
    const int n2  = wc2 * 64;
    const float cs = 0.12751743f;           // (1/sqrt(128)) * log2(e)

    // per-thread tile-load indices
    const int krow = tid >> 5, kc4 = tid & 31;     // K loads: 4 rows apart per i
    const int vrow = tid >> 6, vc4 = tid & 63;     // V loads: 8 rows apart per i

    // ---- prologue: Q, K(0), V(0), mask(0) ----
#pragma unroll
    for (int i = 0; i < 8; i++) {
        int idx = tid + i * 512;
        int row = idx >> 5, k4 = idx & 31;
        *reinterpret_cast<float4*>(&Qs[row * QP + k4 * 4]) =
            *reinterpret_cast<const float4*>(
                &g_inp[(size_t)(b * LL + c0 + row) * DATT + k4 * 4]);
    }
#pragma unroll
    for (int i = 0; i < 4; i++) {
        int row = krow + i * 16;
        *reinterpret_cast<float4*>(&Ks[row * QP + kc4 * 4]) =
            *reinterpret_cast<const float4*>(
                &g_mem[(size_t)(b * LL + row) * DATT + kc4 * 4]);
    }
#pragma unroll
    for (int i = 0; i < 8; i++) {
        int row = vrow + i * 8;
        float4 v = *reinterpret_cast<const float4*>(
            &qryV[(size_t)(b * LL + row) * DIN + vc4 * 4]);
        v.x = f2tf(v.x); v.y = f2tf(v.y); v.z = f2tf(v.z); v.w = f2tf(v.w);
        *reinterpret_cast<float4*>(&Vs[row * VP + vc4 * 4]) = v;
    }
    if (tid < TK) vmsk[tid] = qmask[b * LL + tid];

    float o[2][8][4];
#pragma unroll
    for (int mi = 0; mi < 2; mi++)
#pragma unroll
        for (int j = 0; j < 8; j++)
#pragma unroll
            for (int r = 0; r < 4; r++) o[mi][j][r] = 0.f;
    float lsum0 = 0.f, lsum1 = 0.f;

    __syncthreads();

#pragma unroll 1
    for (int q0 = 0; q0 < LL; q0 += TK) {
        const int q0n = (q0 + TK < LL) ? (q0 + TK) : q0;   // next tile (clamped)

        // ---- GEMM1: S[128,64] = Q.K^T, warp tile 16x32 ----
        float s[4][4];
#pragma unroll
        for (int j = 0; j < 4; j++)
#pragma unroll
            for (int r = 0; r < 4; r++) s[j][r] = 0.f;

#pragma unroll
        for (int k0 = 0; k0 < DATT; k0 += 8) {
            uint32_t a0 = fu(Qs[(r0 + g) * QP + k0 + t]);
            uint32_t a1 = fu(Qs[(r0 + g + 8) * QP + k0 + t]);
            uint32_t a2 = fu(Qs[(r0 + g) * QP + k0 + t + 4]);
            uint32_t a3 = fu(Qs[(r0 + g + 8) * QP + k0 + t + 4]);
#pragma unroll
            for (int j = 0; j < 4; j++) {
                uint32_t b0 = fu(Ks[(nq0 + 8 * j + g) * QP + k0 + t]);
                uint32_t b1 = fu(Ks[(nq0 + 8 * j + g) * QP + k0 + t + 4]);
                mma8(s[j], a0, a1, a2, a3, b0, b1);
            }
        }

        // ---- prefetch K(i+1) into regs (latency hides under softmax) ----
        float4 kk[4];
#pragma unroll
        for (int i = 0; i < 4; i++) {
            int row = krow + i * 16;
            kk[i] = *reinterpret_cast<const float4*>(
                &g_mem[(size_t)(b * LL + q0n + row) * DATT + kc4 * 4]);
        }
        int mv = 0;
        if (tid < TK) mv = qmask[b * LL + q0n + tid];

        // ---- fixed-max softmax: p = exp2(s*cs), masked -> 0 ----
        {
            const int cg0 = c0 + r0 + g, cg1 = cg0 + 8;
            float su0 = 0.f, su1 = 0.f;
#pragma unroll
            for (int j = 0; j < 4; j++) {
                int cl = nq0 + 8 * j + 2 * t;
                bool v0 = vmsk[cl] > 0, v1 = vmsk[cl + 1] > 0;
                int qg0 = q0 + cl, qg1 = qg0 + 1;
                float p00 = (v0 && cg0 != qg0) ? fex2(s[j][0] * cs) : 0.f;
                float p01 = (v1 && cg0 != qg1) ? fex2(s[j][1] * cs) : 0.f;
                float p10 = (v0 && cg1 != qg0) ? fex2(s[j][2] * cs) : 0.f;
                float p11 = (v1 && cg1 != qg1) ? fex2(s[j][3] * cs) : 0.f;
                su0 += p00 + p01;
                su1 += p10 + p11;
                *reinterpret_cast<float2*>(&Ps[(r0 + g) * PP + cl]) =
                    make_float2(f2tf(p00), f2tf(p01));
                *reinterpret_cast<float2*>(&Ps[(r0 + g + 8) * PP + cl]) =
                    make_float2(f2tf(p10), f2tf(p11));
            }
            su0 += __shfl_xor_sync(0xffffffffu, su0, 1);
            su0 += __shfl_xor_sync(0xffffffffu, su0, 2);
            su1 += __shfl_xor_sync(0xffffffffu, su1, 1);
            su1 += __shfl_xor_sync(0xffffffffu, su1, 2);
            lsum0 += su0;
            lsum1 += su1;
        }
        __syncthreads();   // sync_C: Ps ready, GEMM1 done reading Ks

        // ---- store prefetched K(i+1) (Ks now free) ----
#pragma unroll
        for (int i = 0; i < 4; i++) {
            int row = krow + i * 16;
            *reinterpret_cast<float4*>(&Ks[row * QP + kc4 * 4]) = kk[i];
        }

        // ---- GEMM2: O[128,256] += P[128,64] . V[64,256], warp tile 32x64 ----
#pragma unroll
        for (int k0 = 0; k0 < TK; k0 += 8) {
            uint32_t a[2][4];
#pragma unroll
            for (int mi = 0; mi < 2; mi++) {
                int rr = r2 + 16 * mi + g;
                a[mi][0] = fu(Ps[rr * PP + k0 + t]);
                a[mi][1] = fu(Ps[(rr + 8) * PP + k0 + t]);
                a[mi][2] = fu(Ps[rr * PP + k0 + t + 4]);
                a[mi][3] = fu(Ps[(rr + 8) * PP + k0 + t + 4]);
            }
#pragma unroll
            for (int j = 0; j < 8; j++) {
                uint32_t b0 = fu(Vs[(k0 + t) * VP + n2 + 8 * j + g]);
                uint32_t b1 = fu(Vs[(k0 + t + 4) * VP + n2 + 8 * j + g]);
#pragma unroll
                for (int mi = 0; mi < 2; mi++)
                    mma8(o[mi][j], a[mi][0], a[mi][1], a[mi][2], a[mi][3], b0, b1);
            }
        }

        // ---- prefetch V(i+1): LDGs issue now, drain during barrier ----
        float4 vv[8];
#pragma unroll
        for (int i = 0; i < 8; i++) {
            int row = vrow + i * 8;
            vv[i] = *reinterpret_cast<const float4*>(
                &qryV[(size_t)(b * LL + q0n + row) * DIN + vc4 * 4]);
        }
        __syncthreads();   // sync_A: GEMM2 done reading Vs/Ps

        // ---- store V(i+1) + mask(i+1) ----
#pragma unroll
        for (int i = 0; i < 8; i++) {
            int row = vrow + i * 8;
            float4 v = vv[i];
            v.x = f2tf(v.x); v.y = f2tf(v.y); v.z = f2tf(v.z); v.w = f2tf(v.w);
            *reinterpret_cast<float4*>(&Vs[row * VP + vc4 * 4]) = v;
        }
        if (tid < TK) vmsk[tid] = mv;
        __syncthreads();   // sync_B: tiles for iter i+1 visible
    }

    // ---- per-colgroup row sums -> normalize + store ----
    if (t == 0) {
        redL[wc * TQ + r0 + g]     = lsum0;
        redL[wc * TQ + r0 + g + 8] = lsum1;
    }
    __syncthreads();

#pragma unroll
    for (int mi = 0; mi < 2; mi++) {
        int rr0 = r2 + 16 * mi + g;
        int rr1 = rr0 + 8;
        float l0 = 1.0f / (redL[rr0] + redL[TQ + rr0]);
        float l1 = 1.0f / (redL[rr1] + redL[TQ + rr1]);
        size_t rb0 = (size_t)(b * LL + c0 + rr0) * DIN;
        size_t rb1 = (size_t)(b * LL + c0 + rr1) * DIN;
#pragma unroll
        for (int j = 0; j < 8; j++) {
            int cl = n2 + 8 * j + 2 * t;
            *reinterpret_cast<float2*>(&out[rb0 + cl]) =
                make_float2(o[mi][j][0] * l0, o[mi][j][1] * l0);
            *reinterpret_cast<float2*>(&out[rb1 + cl]) =
                make_float2(o[mi][j][2] * l1, o[mi][j][3] * l1);
        }
    }
}

// ---------------------------------------------------------------------------
extern "C" void kernel_launch(void* const* d_in, const int* in_sizes, int n_in,
                              void* d_out, int out_size)
{
    const float* ctx  = (const float*)d_in[0];
    const float* qry  = (const float*)d_in[1];
    const float* Win  = (const float*)d_in[2];
    const float* Wmem = (const float*)d_in[3];
    const int*   msk  = (const int*)d_in[4];
    float* out = (float*)d_out;

    (void)in_sizes; (void)n_in; (void)out_size;

    cudaFuncSetAttribute(attn_kernel,
                         cudaFuncAttributeMaxDynamicSharedMemorySize, SMEMB);

    proj_kernel<<<dim3(BB * LL / 128, 2), 256>>>(ctx, qry, Win, Wmem);
    attn_kernel<<<dim3(LL / TQ, BB), 512, SMEMB>>>(qry, msk, out);
}

// round 11
// speedup vs baseline: 1.2364x; 1.0382x over previous
#include <cuda_runtime.h>
#include <float.h>
#include <math.h>
#include <stdint.h>

#define BB 8
#define LL 2048
#define DIN 256
#define DATT 128

// pair-zipped scratch: within each 8-float k-group, element w stored at
// position zp8(w):  w<4 -> 2w ; w>=4 -> 2(w-4)+1.
// So the mma fragment pair (k0+t, k0+t+4) is contiguous at (k0+2t, k0+2t+1)
// and loads with one LDS.64.
__device__ __align__(128) float g_inp[BB * LL * DATT];  // elu(ctx@W_in), zipped
__device__ __align__(128) float g_mem[BB * LL * DATT];  // elu(qry@W_mem), zipped
__device__ __align__(128) float g_vt [BB * DIN * LL];   // V^T, tf32, q-zipped

__device__ __host__ __forceinline__ int zp8(int w) {
    return (w < 4) ? 2 * w : 2 * (w - 4) + 1;
}
__device__ __host__ __forceinline__ int ZQ(int k) {
    return (k & ~7) | zp8(k & 7);
}

__device__ __forceinline__ float elu01(float v) {
    return v > 0.0f ? v : 0.01f * expm1f(v);
}
__device__ __forceinline__ float f2tf(float v) {
    uint32_t r;
    asm("cvt.rna.tf32.f32 %0, %1;" : "=r"(r) : "f"(v));
    return __uint_as_float(r);
}
__device__ __forceinline__ float fex2(float x) {
    float r;
    asm("ex2.approx.f32 %0, %1;" : "=f"(r) : "f"(x));
    return r;
}
__device__ __forceinline__ uint32_t fu(float v) { return __float_as_uint(v); }

__device__ __forceinline__ void mma8(float d[4],
                                     uint32_t a0, uint32_t a1, uint32_t a2, uint32_t a3,
                                     uint32_t b0, uint32_t b1) {
    asm volatile(
        "mma.sync.aligned.m16n8k8.row.col.f32.tf32.tf32.f32 "
        "{%0,%1,%2,%3},{%4,%5,%6,%7},{%8,%9},{%0,%1,%2,%3};\n"
        : "+f"(d[0]), "+f"(d[1]), "+f"(d[2]), "+f"(d[3])
        : "r"(a0), "r"(a1), "r"(a2), "r"(a3), "r"(b0), "r"(b1));
}

__device__ __forceinline__ void cpa16(uint32_t dst, const float* src) {
    asm volatile("cp.async.cg.shared.global [%0], [%1], 16;\n" :: "r"(dst), "l"(src));
}
#define CPA_COMMIT() asm volatile("cp.async.commit_group;\n" ::: "memory")
#define CPA_WAIT0()  asm volatile("cp.async.wait_group 0;\n" ::: "memory")
#define CPA_WAIT1()  asm volatile("cp.async.wait_group 1;\n" ::: "memory")

// ---------------------------------------------------------------------------
// Kernel 0: vprep — transpose + tf32-round + q-zip V into g_vt[B][256][2048].
// grid (LL/32, DIN/32, BB), block (32, 8).
// ---------------------------------------------------------------------------
__global__ __launch_bounds__(256) void vprep_kernel(const float* __restrict__ qry)
{
    __shared__ float T[32][33];
    const int q0 = blockIdx.x * 32;
    const int d0 = blockIdx.y * 32;
    const int b  = blockIdx.z;
    const int tx = threadIdx.x, ty = threadIdx.y;

#pragma unroll
    for (int r = 0; r < 4; r++) {
        int q = q0 + ty * 4 + r;
        T[ty * 4 + r][tx] = qry[(size_t)(b * LL + q) * DIN + d0 + tx];
    }
    __syncthreads();
#pragma unroll
    for (int r = 0; r < 4; r++) {
        int d = d0 + ty * 4 + r;
        g_vt[(size_t)(b * DIN + d) * LL + ZQ(q0 + tx)] = f2tf(T[tx][ty * 4 + r]);
    }
}

// ---------------------------------------------------------------------------
// Kernel 1: projections on tensor cores, epilogue stores ZIPPED columns.
// grid = (16384/128, 2), block = 256.
// ---------------------------------------------------------------------------
__global__ __launch_bounds__(256) void proj_kernel(
    const float* __restrict__ ctx, const float* __restrict__ qry,
    const float* __restrict__ Win, const float* __restrict__ Wmem)
{
    const int which = blockIdx.y;
    const float* X = (which == 0) ? ctx : qry;
    const float* W = (which == 0) ? Win : Wmem;
    float* O = (which == 0) ? g_inp : g_mem;

    __shared__ float Xs[128 * 36];
    __shared__ float Ws[32 * 136];

    const int tid  = threadIdx.x;
    const int w    = tid >> 5;
    const int lane = tid & 31;
    const int g = lane >> 2;
    const int t = lane & 3;
    const int r0 = (w >> 1) * 32;
    const int n0 = (w & 1) * 64;
    const int m0 = blockIdx.x * 128;

    float acc[2][8][4];
#pragma unroll
    for (int mi = 0; mi < 2; mi++)
#pragma unroll
        for (int j = 0; j < 8; j++)
#pragma unroll
            for (int r = 0; r < 4; r++) acc[mi][j][r] = 0.f;

    for (int kt = 0; kt < 8; kt++) {
#pragma unroll
        for (int i = 0; i < 4; i++) {
            int idx = tid + i * 256;
            int row = idx >> 3, c4 = idx & 7;
            *reinterpret_cast<float4*>(&Xs[row * 36 + c4 * 4]) =
                *reinterpret_cast<const float4*>(
                    &X[(size_t)(m0 + row) * DIN + kt * 32 + c4 * 4]);
        }
#pragma unroll
        for (int i = 0; i < 4; i++) {
            int idx = tid + i * 256;
            int row = idx >> 5, c = idx & 31;
            *reinterpret_cast<float4*>(&Ws[row * 136 + c * 4]) =
                *reinterpret_cast<const float4*>(
                    &W[(size_t)(kt * 32 + row) * DATT + c * 4]);
        }
        __syncthreads();

#pragma unroll
        for (int ks = 0; ks < 4; ks++) {
            int k0 = ks * 8;
            uint32_t a[2][4];
#pragma unroll
            for (int mi = 0; mi < 2; mi++) {
                int rr = r0 + 16 * mi + g;
                a[mi][0] = fu(Xs[rr * 36 + k0 + t]);
                a[mi][1] = fu(Xs[(rr + 8) * 36 + k0 + t]);
                a[mi][2] = fu(Xs[rr * 36 + k0 + t + 4]);
                a[mi][3] = fu(Xs[(rr + 8) * 36 + k0 + t + 4]);
            }
#pragma unroll
            for (int j = 0; j < 8; j++) {
                uint32_t b0 = fu(Ws[(k0 + t) * 136 + n0 + 8 * j + g]);
                uint32_t b1 = fu(Ws[(k0 + t + 4) * 136 + n0 + 8 * j + g]);
#pragma unroll
                for (int mi = 0; mi < 2; mi++)
                    mma8(acc[mi][j], a[mi][0], a[mi][1], a[mi][2], a[mi][3], b0, b1);
            }
        }
        __syncthreads();
    }

    // epilogue: elu + tf32, zipped column positions (cl -> ZQ(cl), cl+1 -> ZQ(cl)+2)
#pragma unroll
    for (int mi = 0; mi < 2; mi++) {
        float* O0 = O + (size_t)(m0 + r0 + 16 * mi + g) * DATT;
        float* O1 = O0 + (size_t)8 * DATT;
#pragma unroll
        for (int j = 0; j < 8; j++) {
            int cl = n0 + 8 * j + 2 * t;
            int z0 = ZQ(cl);
            O0[z0]     = f2tf(elu01(acc[mi][j][0]));
            O0[z0 + 2] = f2tf(elu01(acc[mi][j][1]));
            O1[z0]     = f2tf(elu01(acc[mi][j][2]));
            O1[z0 + 2] = f2tf(elu01(acc[mi][j][3]));
        }
    }
}

// ---------------------------------------------------------------------------
// Kernel 2: fused flash attention.  All operand tiles via cp.async from
// pre-zipped gmem; fragment loads are LDS.64.  grid (16,8), block 512.
// ---------------------------------------------------------------------------
#define TQ 128
#define TK 64
#define QP2 136   // Qs/Ks pitch (mod 32 == 8 -> 8g+2t spans all banks)
#define VTP 72    // VT pitch   (mod 32 == 8)
#define PP 68     // Ps pitch (plain layout)

#define OFF_Q   0
#define OFF_K   (OFF_Q + TQ * QP2)            // 17408
#define OFF_VT  (OFF_K + TK * QP2)            // 26112
#define OFF_P   (OFF_VT + DIN * VTP)          // 44544
#define OFF_L   (OFF_P + TQ * PP)             // 53248
#define OFF_MSK (OFF_L + 2 * TQ)              // 53504
#define SMEMF   (OFF_MSK + TK)                // 53568 floats
#define SMEMB   (SMEMF * 4)                   // 214272 bytes

__global__ __launch_bounds__(512, 1) void attn_kernel(
    const int*   __restrict__ qmask,     // [B,L]
    float*       __restrict__ out)       // [B,L,256]
{
    extern __shared__ float sm[];
    float* Qs   = sm + OFF_Q;
    float* Ks   = sm + OFF_K;
    float* VT   = sm + OFF_VT;
    float* Ps   = sm + OFF_P;
    float* redL = sm + OFF_L;
    int*   vmsk = reinterpret_cast<int*>(sm + OFF_MSK);
    const uint32_t smb = (uint32_t)__cvta_generic_to_shared(sm);

    const int b   = blockIdx.y;
    const int c0  = blockIdx.x * TQ;
    const int tid = threadIdx.x;
    const int w    = tid >> 5;
    const int lane = tid & 31;
    const int g = lane >> 2;
    const int t = lane & 3;
    const int wr  = w >> 1, wc  = w & 1;    // GEMM1: 8 rowgrp x 2 colgrp
    const int wr2 = w >> 2, wc2 = w & 3;    // GEMM2: 4 rowgrp x 4 colgrp
    const int r0  = wr * 16;
    const int nq0 = wc * 32;
    const int r2  = wr2 * 32;
    const int n2  = wc2 * 64;
    const float cs = 0.12751743f;           // (1/sqrt(128)) * log2(e)

    // cp.async thread mappings
    const int qrow = tid >> 5, qch = tid & 31;   // Q/K: 32 chunks of 16B per row
    const int vdv  = tid >> 4, vch = tid & 15;   // VT: 16 chunks per dv-row

    // ---- prologue: issue Q + K(0) (group A), V(0) (group B), mask(0) ----
#pragma unroll
    for (int i = 0; i < 8; i++) {
        int row = qrow + i * 16;
        cpa16(smb + (uint32_t)(OFF_Q + row * QP2 + qch * 4) * 4u,
              &g_inp[(size_t)(b * LL + c0 + row) * DATT + qch * 4]);
    }
#pragma unroll
    for (int i = 0; i < 2; i++) {
        int row = qrow + i * 16 + ((i == 1) ? 16 : 0);   // rows 0..15, 32..47? no:
        (void)row;
    }
    // K(0): 64 rows x 32 chunks = 2048 / 512 = 4 per thread
#pragma unroll
    for (int i = 0; i < 4; i++) {
        int row = qrow + i * 16;
        cpa16(smb + (uint32_t)(OFF_K + row * QP2 + qch * 4) * 4u,
              &g_mem[(size_t)(b * LL + row) * DATT + qch * 4]);
    }
    CPA_COMMIT();   // group: {Q, K0}
    // V(0): 256 dv-rows x 16 chunks = 4096 / 512 = 8 per thread
#pragma unroll
    for (int i = 0; i < 8; i++) {
        int dv = vdv + i * 32;
        cpa16(smb + (uint32_t)(OFF_VT + dv * VTP + vch * 4) * 4u,
              &g_vt[(size_t)(b * DIN + dv) * LL + vch * 4]);
    }
    CPA_COMMIT();   // group: {V0}
    if (tid < TK) vmsk[tid] = qmask[b * LL + tid];

    float o[2][8][4];
#pragma unroll
    for (int mi = 0; mi < 2; mi++)
#pragma unroll
        for (int j = 0; j < 8; j++)
#pragma unroll
            for (int r = 0; r < 4; r++) o[mi][j][r] = 0.f;
    float lsum0 = 0.f, lsum1 = 0.f;

#pragma unroll 1
    for (int q0 = 0; q0 < LL; q0 += TK) {
        const int q0n = (q0 + TK < LL) ? (q0 + TK) : q0;

        CPA_WAIT1();       // K(i) (+Q) complete, per-thread
        __syncthreads();   // sync_top: K(i)/vmsk(i) visible to all

        // ---- GEMM1: S[128,64] = Q.K^T (LDS.64 pair fragments) ----
        float s[4][4];
#pragma unroll
        for (int j = 0; j < 4; j++)
#pragma unroll
            for (int r = 0; r < 4; r++) s[j][r] = 0.f;

        const int qa0 = (r0 + g) * QP2 + 2 * t;
        const int qa1 = (r0 + g + 8) * QP2 + 2 * t;
#pragma unroll
        for (int k0 = 0; k0 < DATT; k0 += 8) {
            float2 pa = *reinterpret_cast<const float2*>(&Qs[qa0 + k0]);  // (a0,a2)
            float2 pb = *reinterpret_cast<const float2*>(&Qs[qa1 + k0]);  // (a1,a3)
#pragma unroll
            for (int j = 0; j < 4; j++) {
                float2 kb = *reinterpret_cast<const float2*>(
                    &Ks[(nq0 + 8 * j + g) * QP2 + k0 + 2 * t]);           // (b0,b1)
                mma8(s[j], fu(pa.x), fu(pb.x), fu(pa.y), fu(pb.y), fu(kb.x), fu(kb.y));
            }
        }

        // mask(i+1) prefetch
        int mv = 0;
        if (tid < TK) mv = qmask[b * LL + q0n + tid];

        // ---- fixed-max softmax: p = exp2(s*cs), masked -> 0 ----
        {
            const int cg0 = c0 + r0 + g, cg1 = cg0 + 8;
            float su0 = 0.f, su1 = 0.f;
#pragma unroll
            for (int j = 0; j < 4; j++) {
                int cl = nq0 + 8 * j + 2 * t;
                bool v0 = vmsk[cl] > 0, v1 = vmsk[cl + 1] > 0;
                int qg0 = q0 + cl, qg1 = qg0 + 1;
                float p00 = (v0 && cg0 != qg0) ? fex2(s[j][0] * cs) : 0.f;
                float p01 = (v1 && cg0 != qg1) ? fex2(s[j][1] * cs) : 0.f;
                float p10 = (v0 && cg1 != qg0) ? fex2(s[j][2] * cs) : 0.f;
                float p11 = (v1 && cg1 != qg1) ? fex2(s[j][3] * cs) : 0.f;
                su0 += p00 + p01;
                su1 += p10 + p11;
                *reinterpret_cast<float2*>(&Ps[(r0 + g) * PP + cl]) =
                    make_float2(f2tf(p00), f2tf(p01));
                *reinterpret_cast<float2*>(&Ps[(r0 + g + 8) * PP + cl]) =
                    make_float2(f2tf(p10), f2tf(p11));
            }
            su0 += __shfl_xor_sync(0xffffffffu, su0, 1);
            su0 += __shfl_xor_sync(0xffffffffu, su0, 2);
            su1 += __shfl_xor_sync(0xffffffffu, su1, 1);
            su1 += __shfl_xor_sync(0xffffffffu, su1, 2);
            lsum0 += su0;
            lsum1 += su1;
        }

        CPA_WAIT0();       // V(i) complete, per-thread
        __syncthreads();   // sync_C: Ps + V(i) visible; Ks free for overwrite

        // issue K(i+1); store mask(i+1)
        if (q0n != q0) {
#pragma unroll
            for (int i = 0; i < 4; i++) {
                int row = qrow + i * 16;
                cpa16(smb + (uint32_t)(OFF_K + row * QP2 + qch * 4) * 4u,
                      &g_mem[(size_t)(b * LL + q0n + row) * DATT + qch * 4]);
            }
            CPA_COMMIT();
        }
        if (tid < TK) vmsk[tid] = mv;

        // ---- GEMM2: O[128,256] += P . V  (VT LDS.64 B-fragments) ----
#pragma unroll
        for (int k0 = 0; k0 < TK; k0 += 8) {
            uint32_t a[2][4];
#pragma unroll
            for (int mi = 0; mi < 2; mi++) {
                int rr = r2 + 16 * mi + g;
                a[mi][0] = fu(Ps[rr * PP + k0 + t]);
                a[mi][1] = fu(Ps[(rr + 8) * PP + k0 + t]);
                a[mi][2] = fu(Ps[rr * PP + k0 + t + 4]);
                a[mi][3] = fu(Ps[(rr + 8) * PP + k0 + t + 4]);
            }
#pragma unroll
            for (int j = 0; j < 8; j++) {
                float2 vb = *reinterpret_cast<const float2*>(
                    &VT[(n2 + 8 * j + g) * VTP + k0 + 2 * t]);            // (b0,b1)
#pragma unroll
                for (int mi = 0; mi < 2; mi++)
                    mma8(o[mi][j], a[mi][0], a[mi][1], a[mi][2], a[mi][3],
                         fu(vb.x), fu(vb.y));
            }
        }

        __syncthreads();   // sync_A: all GEMM2 reads of VT(i) done

        // issue V(i+1)
        if (q0n != q0) {
#pragma unroll
            for (int i = 0; i < 8; i++) {
                int dv = vdv + i * 32;
                cpa16(smb + (uint32_t)(OFF_VT + dv * VTP + vch * 4) * 4u,
                      &g_vt[(size_t)(b * DIN + dv) * LL + q0n + vch * 4]);
            }
            CPA_COMMIT();
        }
    }

    CPA_WAIT0();
    // ---- per-colgroup row sums -> normalize + store ----
    if (t == 0) {
        redL[wc * TQ + r0 + g]     = lsum0;
        redL[wc * TQ + r0 + g + 8] = lsum1;
    }
    __syncthreads();

#pragma unroll
    for (int mi = 0; mi < 2; mi++) {
        int rr0 = r2 + 16 * mi + g;
        int rr1 = rr0 + 8;
        float l0 = 1.0f / (redL[rr0] + redL[TQ + rr0]);
        float l1 = 1.0f / (redL[rr1] + redL[TQ + rr1]);
        size_t rb0 = (size_t)(b * LL + c0 + rr0) * DIN;
        size_t rb1 = (size_t)(b * LL + c0 + rr1) * DIN;
#pragma unroll
        for (int j = 0; j < 8; j++) {
            int cl = n2 + 8 * j + 2 * t;
            *reinterpret_cast<float2*>(&out[rb0 + cl]) =
                make_float2(o[mi][j][0] * l0, o[mi][j][1] * l0);
            *reinterpret_cast<float2*>(&out[rb1 + cl]) =
                make_float2(o[mi][j][2] * l1, o[mi][j][3] * l1);
        }
    }
}

// ---------------------------------------------------------------------------
extern "C" void kernel_launch(void* const* d_in, const int* in_sizes, int n_in,
                              void* d_out, int out_size)
{
    const float* ctx  = (const float*)d_in[0];
    const float* qry  = (const float*)d_in[1];
    const float* Win  = (const float*)d_in[2];
    const float* Wmem = (const float*)d_in[3];
    const int*   msk  = (const int*)d_in[4];
    float* out = (float*)d_out;

    (void)in_sizes; (void)n_in; (void)out_size;

    cudaFuncSetAttribute(attn_kernel,
                         cudaFuncAttributeMaxDynamicSharedMemorySize, SMEMB);

    vprep_kernel<<<dim3(LL / 32, DIN / 32, BB), dim3(32, 8)>>>(qry);
    proj_kernel<<<dim3(BB * LL / 128, 2), 256>>>(ctx, qry, Win, Wmem);
    attn_kernel<<<dim3(LL / TQ, BB), 512, SMEMB>>>(msk, out);
}